// round 7
// baseline (speedup 1.0000x reference)
#include <cuda_runtime.h>
#include <math.h>

// Fused SNN spike layer (R7): eager zero-store + direct chunk counts.
//  LZ: one thread per 16-float chunk: 4 consecutive LDG.128 + 4 STG.128
//      UNCONDITIONAL zeros to out (write stream starts immediately; flagged
//      rows are rewritten later by S3 after a __syncthreads). Per-chunk
//      nonzero count -> shared (single stage).
//  C : rigorous overestimate u[t in chunk C] <= sum_d M[d]*cnt[C-d],
//      M[d] = max srm tap over the chunk-lag range (from actual srm).
//      Refractory <= 0 => unflagged rows can never spike; already zeroed.
//  S2: flagged rows -> EXACT truncated-u recurrence max. max u < theta =>
//      u_eff == u before any spike => all-zero output (already written).
//  S3: rows with max u >= theta -> full exact scan, overwrites the row.

#define T_LEN    300
#define R        26            // rows per block
#define NTH      512
#define NCH16    19            // chunks per row
#define NCHB     (R * NCH16)   // 494 chunks per block
#define CCSTR    20
#define PENDN    16
#define NDELTA   8
#define THETA    10.0f

__global__ __launch_bounds__(NTH, 4)
void snn_r7_kernel(const float* __restrict__ x,
                   const float* __restrict__ refk,
                   const float* __restrict__ srm,
                   float* __restrict__ out,
                   int B, int Ksrm, int Kref)
{
    __shared__ unsigned char cc[R * CCSTR];
    __shared__ unsigned char flag[R];
    __shared__ unsigned char list[R];
    __shared__ int nlist;
    __shared__ float s_M[NDELTA];
    __shared__ float s_rt[PENDN];

    const int tid  = threadIdx.x;
    const int row0 = blockIdx.x * R;

    if (tid < R) flag[tid] = 0;
    if (tid == 0) nlist = 0;
    if (tid < PENDN) {
        float v = 0.0f;
        if (tid + 1 < Kref) v = refk[tid + 1];
        s_rt[tid] = v;
    }
    if (tid < NDELTA) {
        int lo = 16 * tid - 15; if (lo < 0) lo = 0;
        int hi = 16 * tid + 15; if (hi > Ksrm - 1) hi = Ksrm - 1;
        float m = 0.0f;
        for (int k = lo; k <= hi; ++k) m = fmaxf(m, srm[k]);
        s_M[tid] = m;
    }

    // ---- LZ: load chunk + eager zero-store + direct count ----
    if (tid < NCHB) {
        const int r = tid / NCH16;           // chunk owner row
        const int c = tid - r * NCH16;       // chunk index in row
        const int rowg = row0 + r;
        const int tbase = c * 16;            // first t of chunk
        if (rowg < B) {
            const float4* xr4 = (const float4*)(x + (size_t)rowg * T_LEN);
            float4*       or4 = (float4*)(out + (size_t)rowg * T_LEN);
            const float4  z   = make_float4(0.f, 0.f, 0.f, 0.f);
            int cnt = 0;
#pragma unroll
            for (int j = 0; j < 4; ++j) {
                const int q = (tbase >> 2) + j;      // float4 index in row
                if (tbase + 4 * j < T_LEN) {
                    const float4 v = xr4[q];
                    or4[q] = z;                      // unconditional zero
                    cnt += (v.x != 0.0f) + (v.y != 0.0f)
                         + (v.z != 0.0f) + (v.w != 0.0f);
                }
            }
            cc[r * CCSTR + c] = (unsigned char)cnt;
        } else {
            cc[r * CCSTR + c] = 0;
        }
    }
    __syncthreads();

    // ---- C: weighted-count bound -> row flags ----
    if (tid < NCHB) {
        const int r = tid / NCH16;
        const int C = tid - r * NCH16;
        float bsum = 0.0f;
#pragma unroll
        for (int d = 0; d < NDELTA; ++d) {
            const int c = C - d;
            if (c >= 0) bsum = fmaf(s_M[d], (float)cc[r * CCSTR + c], bsum);
        }
        if (bsum >= THETA - 0.02f) flag[r] = 1;   // benign same-value race
    }
    __syncthreads();

    if (tid < R && flag[tid] && (row0 + tid) < B) {
        const int p = atomicAdd(&nlist, 1);
        list[p] = (unsigned char)tid;
    }
    __syncthreads();   // also orders eager zeros before S3 overwrites

    // ---- S2/S3: flagged rows only ----
    if (tid < nlist) {
        const int r = list[tid];
        const int rowg = row0 + r;

        // recurrence constants (identical derivation to R1/R2/R5)
        const double f1d = (double)srm[1];
        const double f2d = (double)srm[2];
        const double ddd = f2d / (2.0 * f1d);
        const double Add = f1d / ddd;
        const float dcy = (float)ddd;
        const float Af  = (float)Add;
        const float dK  = exp2f((float)Ksrm * log2f(dcy));
        const float C2c = Af * dK;
        const float C1c = Af * (float)Ksrm * dK;

        const float* xr = x + (size_t)rowg * T_LEN;

        // S2: exact truncated-u max (same FMA sequence as the scan's u)
        float s1 = 0.0f, s2 = 0.0f, s1d = 0.0f, s2d = 0.0f, mx = -1e30f;
#pragma unroll 4
        for (int t = 0; t < T_LEN; ++t) {
            const float xv = xr[t];
            const int j2 = t - Ksrm;
            const float xd = (j2 >= 0) ? xr[j2] : 0.0f;
            s2  = dcy * (s2 + s1);
            s1  = fmaf(dcy, s1, xv);
            s2d = dcy * (s2d + s1d);
            s1d = fmaf(dcy, s1d, xd);
            const float u = fmaf(-C1c, s1d, fmaf(-C2c, s2d, Af * s2));
            mx = fmaxf(mx, u);
        }

        if (mx >= THETA) {
            // S3: full exact scan (R1/R2 arithmetic; rel_err == 0 each round)
            float* orow = out + (size_t)rowg * T_LEN;
            s1 = s2 = s1d = s2d = 0.0f;
            float p[PENDN];
#pragma unroll
            for (int j = 0; j < PENDN; ++j) p[j] = 0.0f;

            for (int t = 0; t < T_LEN; ++t) {
                const float xv = xr[t];
                const int j2 = t - Ksrm;
                const float xd = (j2 >= 0) ? xr[j2] : 0.0f;

                s2  = dcy * (s2 + s1);
                s1  = fmaf(dcy, s1, xv);
                s2d = dcy * (s2d + s1d);
                s1d = fmaf(dcy, s1d, xd);

                const float u    = fmaf(-C1c, s1d, fmaf(-C2c, s2d, Af * s2));
                const float ueff = u + p[0];
                const float s    = (ueff >= THETA) ? 1.0f : 0.0f;

#pragma unroll
                for (int j = 0; j < PENDN - 1; ++j)
                    p[j] = fmaf(s, s_rt[j], p[j + 1]);
                p[PENDN - 1] = s * s_rt[PENDN - 1];

                orow[t] = s;
            }
        }
        // mx < THETA: row is exactly zero and already zero-filled -> done.
    }
}

extern "C" void kernel_launch(void* const* d_in, const int* in_sizes, int n_in,
                              void* d_out, int out_size)
{
    const float* x    = (const float*)d_in[0];
    const float* srm  = (const float*)d_in[1];
    const float* refk = (const float*)d_in[2];
    float* out        = (float*)d_out;

    const int total = in_sizes[0];
    const int B     = total / T_LEN;
    const int Ksrm  = in_sizes[1];
    const int Kref  = in_sizes[2];

    const int grid = (B + R - 1) / R;
    snn_r7_kernel<<<grid, NTH>>>(x, refk, srm, out, B, Ksrm, Kref);
}

// round 8
// speedup vs baseline: 1.1320x; 1.1320x over previous
#include <cuda_runtime.h>
#include <math.h>

// Fused SNN spike layer (R8 = R5 + eager coalesced zero-store).
//  L : linear coalesced float4 stream; per-float4 nonzero counts -> shared;
//      SIMULTANEOUS unconditional zero STG.128 to out at the same linear
//      index (write stream overlaps read stream; flagged rows rewritten by
//      S3 after the sync). Lane-linear indexing: 4 lines per LDG/STG.
//  C : 16-chunk counts; rigorous overestimate u <= sum_d M[d]*cnt[C-d]
//      (M from actual srm taps). Refractory <= 0 => unflagged never spike.
//  S2: flagged rows -> EXACT truncated-u recurrence max (no pending).
//      max u < theta => u_eff == u before any spike => exactly zero output
//      (already written).
//  S3: rows with max u >= theta -> full exact scan, overwrites the row.

#define T_LEN    300
#define Q4       75
#define R        26
#define NTH      512
#define NCH16    19
#define CNTSTR   76            // Q4 + 1 pad
#define CCSTR    20
#define PENDN    16
#define NDELTA   8
#define THETA    10.0f

__global__ __launch_bounds__(NTH, 4)
void snn_r8_kernel(const float* __restrict__ x,
                   const float* __restrict__ srm,
                   const float* __restrict__ refk,
                   float* __restrict__ out,
                   int B, int Ksrm, int Kref)
{
    __shared__ unsigned char cnt4[R * CNTSTR];
    __shared__ unsigned char cc[R * CCSTR];
    __shared__ unsigned char flag[R];
    __shared__ unsigned char list[R];
    __shared__ int nlist;
    __shared__ float s_M[NDELTA];
    __shared__ float s_rt[PENDN];

    const int tid  = threadIdx.x;
    const int row0 = blockIdx.x * R;
    const long long g4base = (long long)row0 * Q4;
    const long long g4tot  = (long long)B * Q4;

    if (tid < R) { flag[tid] = 0; cnt4[tid * CNTSTR + Q4] = 0; }
    if (tid == 0) nlist = 0;
    if (tid < PENDN) {
        float v = 0.0f;
        if (tid + 1 < Kref) v = refk[tid + 1];
        s_rt[tid] = v;
    }
    if (tid < NDELTA) {
        int lo = 16 * tid - 15; if (lo < 0) lo = 0;
        int hi = 16 * tid + 15; if (hi > Ksrm - 1) hi = Ksrm - 1;
        float m = 0.0f;
        for (int k = lo; k <= hi; ++k) m = fmaxf(m, srm[k]);
        s_M[tid] = m;
    }

    // ---- L: coalesced load + count + eager unconditional zero-store ----
    const float4* x4 = (const float4*)x;
    float4*       o4 = (float4*)out;
    const float4  z  = make_float4(0.f, 0.f, 0.f, 0.f);
#pragma unroll
    for (int it = 0; it < (R * Q4 + NTH - 1) / NTH; ++it) {
        const int idx = it * NTH + tid;
        if (idx < R * Q4 && g4base + idx < g4tot) {
            const float4 v = x4[g4base + idx];
            o4[g4base + idx] = z;                 // overwritten by S3 if needed
            const int r = idx / Q4;
            const int q = idx - r * Q4;
            int c = (v.x != 0.0f) + (v.y != 0.0f)
                  + (v.z != 0.0f) + (v.w != 0.0f);
            cnt4[r * CNTSTR + q] = (unsigned char)c;
        }
    }
    __syncthreads();

    // ---- C1: 16-chunk counts ----
    if (tid < R * NCH16) {
        const int r = tid / NCH16;
        const int c = tid - r * NCH16;
        const unsigned char* b = cnt4 + r * CNTSTR + 4 * c;
        cc[r * CCSTR + c] = (unsigned char)(b[0] + b[1] + b[2] + b[3]);
    }
    __syncthreads();

    // ---- C2: weighted-count bound -> row flags ----
    if (tid < R * NCH16) {
        const int r = tid / NCH16;
        const int C = tid - r * NCH16;
        float bsum = 0.0f;
#pragma unroll
        for (int d = 0; d < NDELTA; ++d) {
            const int c = C - d;
            if (c >= 0) bsum = fmaf(s_M[d], (float)cc[r * CCSTR + c], bsum);
        }
        if (bsum >= THETA - 0.02f) flag[r] = 1;   // benign same-value race
    }
    __syncthreads();

    if (tid < R && flag[tid] && (row0 + tid) < B) {
        const int p = atomicAdd(&nlist, 1);
        list[p] = (unsigned char)tid;
    }
    __syncthreads();   // orders eager zeros before S3 overwrites (same block)

    // ---- S2/S3: flagged rows only ----
    if (tid < nlist) {
        const int r = list[tid];
        const int rowg = row0 + r;

        // recurrence constants (identical derivation to R1/R2/R5)
        const double f1d = (double)srm[1];
        const double f2d = (double)srm[2];
        const double ddd = f2d / (2.0 * f1d);
        const double Add = f1d / ddd;
        const float dcy = (float)ddd;
        const float Af  = (float)Add;
        const float dK  = exp2f((float)Ksrm * log2f(dcy));
        const float C2c = Af * dK;
        const float C1c = Af * (float)Ksrm * dK;

        const float* xr = x + (size_t)rowg * T_LEN;

        // S2: exact truncated-u max (same FMA sequence as the scan's u)
        float s1 = 0.0f, s2 = 0.0f, s1d = 0.0f, s2d = 0.0f, mx = -1e30f;
#pragma unroll 4
        for (int t = 0; t < T_LEN; ++t) {
            const float xv = xr[t];
            const int j2 = t - Ksrm;
            const float xd = (j2 >= 0) ? xr[j2] : 0.0f;
            s2  = dcy * (s2 + s1);
            s1  = fmaf(dcy, s1, xv);
            s2d = dcy * (s2d + s1d);
            s1d = fmaf(dcy, s1d, xd);
            const float u = fmaf(-C1c, s1d, fmaf(-C2c, s2d, Af * s2));
            mx = fmaxf(mx, u);
        }

        if (mx >= THETA) {
            // S3: full exact scan (R1/R2 arithmetic; rel_err == 0 each round)
            float* orow = out + (size_t)rowg * T_LEN;
            s1 = s2 = s1d = s2d = 0.0f;
            float p[PENDN];
#pragma unroll
            for (int j = 0; j < PENDN; ++j) p[j] = 0.0f;

            for (int t = 0; t < T_LEN; ++t) {
                const float xv = xr[t];
                const int j2 = t - Ksrm;
                const float xd = (j2 >= 0) ? xr[j2] : 0.0f;

                s2  = dcy * (s2 + s1);
                s1  = fmaf(dcy, s1, xv);
                s2d = dcy * (s2d + s1d);
                s1d = fmaf(dcy, s1d, xd);

                const float u    = fmaf(-C1c, s1d, fmaf(-C2c, s2d, Af * s2));
                const float ueff = u + p[0];
                const float s    = (ueff >= THETA) ? 1.0f : 0.0f;

#pragma unroll
                for (int j = 0; j < PENDN - 1; ++j)
                    p[j] = fmaf(s, s_rt[j], p[j + 1]);
                p[PENDN - 1] = s * s_rt[PENDN - 1];

                orow[t] = s;
            }
        }
        // mx < THETA: row already zero-filled -> done.
    }
}

extern "C" void kernel_launch(void* const* d_in, const int* in_sizes, int n_in,
                              void* d_out, int out_size)
{
    const float* x    = (const float*)d_in[0];
    const float* srm  = (const float*)d_in[1];
    const float* refk = (const float*)d_in[2];
    float* out        = (float*)d_out;

    const int total = in_sizes[0];
    const int B     = total / T_LEN;
    const int Ksrm  = in_sizes[1];
    const int Kref  = in_sizes[2];

    const int grid = (B + R - 1) / R;
    snn_r8_kernel<<<grid, NTH>>>(x, srm, refk, out, B, Ksrm, Kref);
}

// round 10
// speedup vs baseline: 1.3361x; 1.1803x over previous
#include <cuda_runtime.h>
#include <math.h>

// Fused SNN spike layer (R9b = R9 with dp4a overload fix): warp-autonomous
// rows, no block-wide sync in the streaming path.
//  Per warp, per row:
//   L : 3 coalesced LDG.128 iters; per-float4 nonzero counts -> private warp
//       buffer (__syncwarp only).
//   C : chunk bound u <= sum_d M[d]*cnt16[C-d] via dp4a on count words
//       (M[d] = max srm tap over chunk-lag range; same rigorous bound as
//       R5, rel_err = 0). Refractory <= 0 => unflagged rows never spike.
//   Z : unflagged -> 3 coalesced STG.128 zeros.
//   S2: flagged -> warp-parallel windowed live recurrence (30 lanes x 10-t
//       windows, <=76-step warmup). Real-arith OVERestimate of truncated u;
//       Af*max < theta - 2e-3 => exact u < theta => row exactly zero.
//   S3: else lane 0 runs the full exact scan (R1/R5 arithmetic).

#define T_LEN    300
#define Q4       75
#define NTH      512
#define WPB      16            // warps per block
#define RPW      2             // rows per warp
#define RPB      (WPB * RPW)   // 32 rows per block
#define NCH16    19
#define PENDN    16
#define NDELTA   8
#define THETA    10.0f
#define MARGIN1  0.02f
#define MARGIN2  2e-3f

__global__ __launch_bounds__(NTH, 4)
void snn_r9_kernel(const float* __restrict__ x,
                   const float* __restrict__ srm,
                   const float* __restrict__ refk,
                   float* __restrict__ out,
                   int B, int Ksrm, int Kref)
{
    __shared__ float s_M[NDELTA];
    __shared__ float s_rt[PENDN];
    __shared__ unsigned int cntw[WPB][20];   // 80B per warp: 75 counts + pad

    const int tid  = threadIdx.x;
    const int lane = tid & 31;
    const int w    = tid >> 5;

    if (tid < PENDN) {
        float v = 0.0f;
        if (tid + 1 < Kref) v = refk[tid + 1];
        s_rt[tid] = v;
    }
    if (tid < NDELTA) {
        int lo = 16 * tid - 15; if (lo < 0) lo = 0;
        int hi = 16 * tid + 15; if (hi > Ksrm - 1) hi = Ksrm - 1;
        float m = 0.0f;
        for (int k = lo; k <= hi; ++k) m = fmaxf(m, srm[k]);
        s_M[tid] = m;
    }
    __syncthreads();   // only block-wide sync

    unsigned char* cw = (unsigned char*)cntw[w];
    const float4 z = make_float4(0.f, 0.f, 0.f, 0.f);

    for (int rr = 0; rr < RPW; ++rr) {
        const int r = blockIdx.x * RPB + w * RPW + rr;
        if (r >= B) break;
        const float4* xr4 = (const float4*)(x + (size_t)r * T_LEN);
        float4*       or4 = (float4*)(out + (size_t)r * T_LEN);

        // ---- L: coalesced load + per-float4 count to warp buffer ----
#pragma unroll
        for (int it = 0; it < 3; ++it) {
            const int q = it * 32 + lane;
            if (q < Q4) {
                const float4 v = xr4[q];
                const int c = (v.x != 0.0f) + (v.y != 0.0f)
                            + (v.z != 0.0f) + (v.w != 0.0f);
                cw[q] = (unsigned char)c;
            } else if (q < Q4 + 5) {
                cw[q] = 0;                    // pad so chunk 18 reads zeros
            }
        }
        __syncwarp();

        // ---- C: chunk bound (dp4a sums 4 counts/word) -> flag ----
        float bsum = 0.0f;
        if (lane < NCH16) {
#pragma unroll
            for (int d = 0; d < NDELTA; ++d) {
                const int c = lane - d;
                if (c >= 0) {
                    const unsigned s = __dp4a(cntw[w][c], 0x01010101u, 0u);
                    bsum = fmaf(s_M[d], (float)s, bsum);
                }
            }
        }
        const bool flagged = __any_sync(0xFFFFFFFFu,
                                        (lane < NCH16) && (bsum >= THETA - MARGIN1));

        if (!flagged) {
            // ---- Z: coalesced zero-fill ----
#pragma unroll
            for (int it = 0; it < 3; ++it) {
                const int q = it * 32 + lane;
                if (q < Q4) or4[q] = z;
            }
        } else {
            // recurrence constants (rare path; identical derivation to R1/R5)
            const double f1d = (double)srm[1];
            const double f2d = (double)srm[2];
            const double ddd = f2d / (2.0 * f1d);
            const double Add = f1d / ddd;
            const float dcy = (float)ddd;
            const float Af  = (float)Add;

            const float* xr = x + (size_t)r * T_LEN;

            // ---- S2: warp-parallel windowed overestimate ----
            float mx = -1e30f;
            if (lane < 30) {
                const int tstart = lane * 10;
                int t0 = tstart - (Ksrm - 1); if (t0 < 0) t0 = 0;
                float s1 = 0.0f, s2 = 0.0f;
                for (int t = t0; t < tstart; ++t) {
                    s2 = dcy * (s2 + s1);
                    s1 = fmaf(dcy, s1, xr[t]);
                }
#pragma unroll
                for (int t = tstart; t < tstart + 10; ++t) {
                    s2 = dcy * (s2 + s1);
                    s1 = fmaf(dcy, s1, xr[t]);
                    mx = fmaxf(mx, s2);
                }
            }
#pragma unroll
            for (int o = 16; o; o >>= 1)
                mx = fmaxf(mx, __shfl_xor_sync(0xFFFFFFFFu, mx, o));

            if (Af * mx < THETA - MARGIN2) {
                // overestimate below theta => exact u < theta => all zero
#pragma unroll
                for (int it = 0; it < 3; ++it) {
                    const int q = it * 32 + lane;
                    if (q < Q4) or4[q] = z;
                }
            } else if (lane == 0) {
                // ---- S3: full exact scan (R1/R5 arithmetic) ----
                const float dK  = exp2f((float)Ksrm * log2f(dcy));
                const float C2c = Af * dK;
                const float C1c = Af * (float)Ksrm * dK;
                float* orow = out + (size_t)r * T_LEN;

                float s1 = 0.0f, s2 = 0.0f, s1d = 0.0f, s2d = 0.0f;
                float p[PENDN];
#pragma unroll
                for (int j = 0; j < PENDN; ++j) p[j] = 0.0f;

                for (int t = 0; t < T_LEN; ++t) {
                    const float xv = xr[t];
                    const int j2 = t - Ksrm;
                    const float xd = (j2 >= 0) ? xr[j2] : 0.0f;

                    s2  = dcy * (s2 + s1);
                    s1  = fmaf(dcy, s1, xv);
                    s2d = dcy * (s2d + s1d);
                    s1d = fmaf(dcy, s1d, xd);

                    const float u    = fmaf(-C1c, s1d, fmaf(-C2c, s2d, Af * s2));
                    const float ueff = u + p[0];
                    const float s    = (ueff >= THETA) ? 1.0f : 0.0f;

#pragma unroll
                    for (int j = 0; j < PENDN - 1; ++j)
                        p[j] = fmaf(s, s_rt[j], p[j + 1]);
                    p[PENDN - 1] = s * s_rt[PENDN - 1];

                    orow[t] = s;
                }
            }
        }
    }
}

extern "C" void kernel_launch(void* const* d_in, const int* in_sizes, int n_in,
                              void* d_out, int out_size)
{
    const float* x    = (const float*)d_in[0];
    const float* srm  = (const float*)d_in[1];
    const float* refk = (const float*)d_in[2];
    float* out        = (float*)d_out;

    const int total = in_sizes[0];
    const int B     = total / T_LEN;
    const int Ksrm  = in_sizes[1];
    const int Kref  = in_sizes[2];

    const int grid = (B + RPB - 1) / RPB;
    snn_r9_kernel<<<grid, NTH>>>(x, srm, refk, out, B, Ksrm, Kref);
}

// round 11
// speedup vs baseline: 1.4183x; 1.0615x over previous
#include <cuda_runtime.h>
#include <math.h>

// Fused SNN spike layer (R10): warp-autonomous, software-pipelined row pairs.
//  Per warp: rows rA=2w, rA+1 (contiguous).
//   loadA -> countsA -> [issue loadB] -> boundA -> countsB -> handleA
//          -> boundB -> handleB
//  Bound: u <= sum_d M[d]*cnt16[C-d] (M[d] = max srm tap over chunk-lag
//  range; rigorous, from actual srm). Refractory <= 0 => unflagged rows
//  never spike -> STG.128 zeros (streaming .cs hints; rows touched once).
//  S2: flagged -> warp-parallel windowed live recurrence overestimate;
//      Af*max < theta - 2e-3 => exact u < theta => row exactly zero.
//  S3: else lane 0 full exact scan (R1/R5 arithmetic; rel_err = 0 5 rounds).

#define T_LEN    300
#define Q4       75
#define NTH      512
#define WPB      16
#define RPB      (WPB * 2)     // 32 rows per block
#define NCH16    19
#define PENDN    16
#define NDELTA   8
#define THETA    10.0f
#define MARGIN1  0.02f
#define MARGIN2  2e-3f

__global__ __launch_bounds__(NTH, 3)
void snn_r10_kernel(const float* __restrict__ x,
                    const float* __restrict__ srm,
                    const float* __restrict__ refk,
                    float* __restrict__ out,
                    int B, int Ksrm, int Kref)
{
    __shared__ float s_M[NDELTA];
    __shared__ float s_rt[PENDN];
    __shared__ unsigned int cntw[WPB][2][20];   // double-buffered counts/warp

    const int tid  = threadIdx.x;
    const int lane = tid & 31;
    const int w    = tid >> 5;

    if (tid < PENDN) {
        float v = 0.0f;
        if (tid + 1 < Kref) v = refk[tid + 1];
        s_rt[tid] = v;
    }
    if (tid < NDELTA) {
        int lo = 16 * tid - 15; if (lo < 0) lo = 0;
        int hi = 16 * tid + 15; if (hi > Ksrm - 1) hi = Ksrm - 1;
        float m = 0.0f;
        for (int k = lo; k <= hi; ++k) m = fmaxf(m, srm[k]);
        s_M[tid] = m;
    }
    __syncthreads();   // only block-wide sync

    const float4 z = make_float4(0.f, 0.f, 0.f, 0.f);
    const int rA = blockIdx.x * RPB + w * 2;
    const int rB = rA + 1;

    const float4* xA4 = (const float4*)(x + (size_t)rA * T_LEN);
    const float4* xB4 = (const float4*)(x + (size_t)rB * T_LEN);

    // ---- load A (3 coalesced LDG.128, streaming) ----
    float4 a0 = z, a1 = z, a2 = z;
    if (rA < B) {
        a0 = __ldcs(xA4 + lane);
        a1 = __ldcs(xA4 + 32 + lane);
        if (lane < Q4 - 64) a2 = __ldcs(xA4 + 64 + lane);
    }

    // ---- counts A -> slot 0 (A values die here) ----
    {
        unsigned char* cb = (unsigned char*)cntw[w][0];
        cb[lane] = (unsigned char)((a0.x != 0.f) + (a0.y != 0.f)
                                 + (a0.z != 0.f) + (a0.w != 0.f));
        cb[32 + lane] = (unsigned char)((a1.x != 0.f) + (a1.y != 0.f)
                                      + (a1.z != 0.f) + (a1.w != 0.f));
        if (lane < Q4 - 64)
            cb[64 + lane] = (unsigned char)((a2.x != 0.f) + (a2.y != 0.f)
                                          + (a2.z != 0.f) + (a2.w != 0.f));
        else if (lane < 16)
            cb[64 + lane] = 0;               // pad bytes 75..79
        __syncwarp();
    }

    // ---- issue load B early (overlaps bound A) ----
    float4 b0 = z, b1 = z, b2 = z;
    if (rB < B) {
        b0 = __ldcs(xB4 + lane);
        b1 = __ldcs(xB4 + 32 + lane);
        if (lane < Q4 - 64) b2 = __ldcs(xB4 + 64 + lane);
    }

    // ---- bound A ----
    bool flagA;
    {
        float bsum = 0.0f;
        if (lane < NCH16) {
#pragma unroll
            for (int d = 0; d < NDELTA; ++d) {
                const int c = lane - d;
                if (c >= 0) {
                    const unsigned s = __dp4a(cntw[w][0][c], 0x01010101u, 0u);
                    bsum = fmaf(s_M[d], (float)s, bsum);
                }
            }
        }
        flagA = __any_sync(0xFFFFFFFFu,
                           (lane < NCH16) && (bsum >= THETA - MARGIN1));
    }

    // ---- counts B -> slot 1 (B values die before any divergence) ----
    {
        unsigned char* cb = (unsigned char*)cntw[w][1];
        cb[lane] = (unsigned char)((b0.x != 0.f) + (b0.y != 0.f)
                                 + (b0.z != 0.f) + (b0.w != 0.f));
        cb[32 + lane] = (unsigned char)((b1.x != 0.f) + (b1.y != 0.f)
                                      + (b1.z != 0.f) + (b1.w != 0.f));
        if (lane < Q4 - 64)
            cb[64 + lane] = (unsigned char)((b2.x != 0.f) + (b2.y != 0.f)
                                          + (b2.z != 0.f) + (b2.w != 0.f));
        else if (lane < 16)
            cb[64 + lane] = 0;
        __syncwarp();
    }

    // ---- per-row handler (zero / S2 / S3), identical math to R9b ----
    auto handle_row = [&](int r, bool flagged) {
        if (r >= B) return;
        float4* or4 = (float4*)(out + (size_t)r * T_LEN);
        if (!flagged) {
            __stcs(or4 + lane, z);
            __stcs(or4 + 32 + lane, z);
            if (lane < Q4 - 64) __stcs(or4 + 64 + lane, z);
            return;
        }
        // rare path: recurrence constants (identical derivation to R1/R5)
        const double f1d = (double)srm[1];
        const double f2d = (double)srm[2];
        const double ddd = f2d / (2.0 * f1d);
        const double Add = f1d / ddd;
        const float dcy = (float)ddd;
        const float Af  = (float)Add;
        const float* xr = x + (size_t)r * T_LEN;

        // S2: warp-parallel windowed overestimate
        float mx = -1e30f;
        if (lane < 30) {
            const int tstart = lane * 10;
            int t0 = tstart - (Ksrm - 1); if (t0 < 0) t0 = 0;
            float s1 = 0.0f, s2 = 0.0f;
            for (int t = t0; t < tstart; ++t) {
                s2 = dcy * (s2 + s1);
                s1 = fmaf(dcy, s1, xr[t]);
            }
#pragma unroll
            for (int t = tstart; t < tstart + 10; ++t) {
                s2 = dcy * (s2 + s1);
                s1 = fmaf(dcy, s1, xr[t]);
                mx = fmaxf(mx, s2);
            }
        }
#pragma unroll
        for (int o = 16; o; o >>= 1)
            mx = fmaxf(mx, __shfl_xor_sync(0xFFFFFFFFu, mx, o));

        if (Af * mx < THETA - MARGIN2) {
            __stcs(or4 + lane, z);
            __stcs(or4 + 32 + lane, z);
            if (lane < Q4 - 64) __stcs(or4 + 64 + lane, z);
        } else if (lane == 0) {
            // S3: full exact scan
            const float dK  = exp2f((float)Ksrm * log2f(dcy));
            const float C2c = Af * dK;
            const float C1c = Af * (float)Ksrm * dK;
            float* orow = out + (size_t)r * T_LEN;

            float s1 = 0.0f, s2 = 0.0f, s1d = 0.0f, s2d = 0.0f;
            float p[PENDN];
#pragma unroll
            for (int j = 0; j < PENDN; ++j) p[j] = 0.0f;

            for (int t = 0; t < T_LEN; ++t) {
                const float xv = xr[t];
                const int j2 = t - Ksrm;
                const float xd = (j2 >= 0) ? xr[j2] : 0.0f;

                s2  = dcy * (s2 + s1);
                s1  = fmaf(dcy, s1, xv);
                s2d = dcy * (s2d + s1d);
                s1d = fmaf(dcy, s1d, xd);

                const float u    = fmaf(-C1c, s1d, fmaf(-C2c, s2d, Af * s2));
                const float ueff = u + p[0];
                const float s    = (ueff >= THETA) ? 1.0f : 0.0f;

#pragma unroll
                for (int j = 0; j < PENDN - 1; ++j)
                    p[j] = fmaf(s, s_rt[j], p[j + 1]);
                p[PENDN - 1] = s * s_rt[PENDN - 1];

                orow[t] = s;
            }
        }
    };

    handle_row(rA, flagA);

    // ---- bound B ----
    bool flagB;
    {
        float bsum = 0.0f;
        if (lane < NCH16) {
#pragma unroll
            for (int d = 0; d < NDELTA; ++d) {
                const int c = lane - d;
                if (c >= 0) {
                    const unsigned s = __dp4a(cntw[w][1][c], 0x01010101u, 0u);
                    bsum = fmaf(s_M[d], (float)s, bsum);
                }
            }
        }
        flagB = __any_sync(0xFFFFFFFFu,
                           (lane < NCH16) && (bsum >= THETA - MARGIN1));
    }

    handle_row(rB, flagB);
}

extern "C" void kernel_launch(void* const* d_in, const int* in_sizes, int n_in,
                              void* d_out, int out_size)
{
    const float* x    = (const float*)d_in[0];
    const float* srm  = (const float*)d_in[1];
    const float* refk = (const float*)d_in[2];
    float* out        = (float*)d_out;

    const int total = in_sizes[0];
    const int B     = total / T_LEN;
    const int Ksrm  = in_sizes[1];
    const int Kref  = in_sizes[2];

    const int grid = (B + RPB - 1) / RPB;
    snn_r10_kernel<<<grid, NTH>>>(x, srm, refk, out, B, Ksrm, Kref);
}

// round 12
// speedup vs baseline: 1.4390x; 1.0146x over previous
#include <cuda_runtime.h>
#include <math.h>

// Fused SNN spike layer (R11 = R10 + float-sum counts).
//  Per warp: pipelined row pair (loadA -> sumsA -> loadB -> boundA -> sumsB
//  -> handleA -> boundB -> handleB).
//  Counts are float SUMS (x in {0,1} -> sum == nonzero count; 3 FADD + F2I
//  instead of 4 FSETP + IADD chains). Bound u <= sum_d M[d]*sum16[C-d] is
//  the direct Hoelder bound, valid for any nonnegative x. Refractory <= 0
//  => unflagged rows never spike -> STG.128 zeros (.cs streaming).
//  S2: flagged -> warp-parallel windowed live-recurrence overestimate;
//      Af*max < theta - 2e-3 => exact u < theta => row exactly zero.
//  S3: else lane 0 full exact scan (R1/R5 arithmetic; rel_err = 0 6 rounds).

#define T_LEN    300
#define Q4       75
#define NTH      512
#define WPB      16
#define RPB      (WPB * 2)     // 32 rows per block
#define NCH16    19
#define PENDN    16
#define NDELTA   8
#define THETA    10.0f
#define MARGIN1  0.02f
#define MARGIN2  2e-3f

__global__ __launch_bounds__(NTH, 3)
void snn_r11_kernel(const float* __restrict__ x,
                    const float* __restrict__ srm,
                    const float* __restrict__ refk,
                    float* __restrict__ out,
                    int B, int Ksrm, int Kref)
{
    __shared__ float s_M[NDELTA];
    __shared__ float s_rt[PENDN];
    __shared__ unsigned int cntw[WPB][2][20];   // double-buffered sums/warp

    const int tid  = threadIdx.x;
    const int lane = tid & 31;
    const int w    = tid >> 5;

    if (tid < PENDN) {
        float v = 0.0f;
        if (tid + 1 < Kref) v = refk[tid + 1];
        s_rt[tid] = v;
    }
    if (tid < NDELTA) {
        int lo = 16 * tid - 15; if (lo < 0) lo = 0;
        int hi = 16 * tid + 15; if (hi > Ksrm - 1) hi = Ksrm - 1;
        float m = 0.0f;
        for (int k = lo; k <= hi; ++k) m = fmaxf(m, srm[k]);
        s_M[tid] = m;
    }
    __syncthreads();   // only block-wide sync

    const float4 z = make_float4(0.f, 0.f, 0.f, 0.f);
    const int rA = blockIdx.x * RPB + w * 2;
    const int rB = rA + 1;

    const float4* xA4 = (const float4*)(x + (size_t)rA * T_LEN);
    const float4* xB4 = (const float4*)(x + (size_t)rB * T_LEN);

    // ---- load A (3 coalesced LDG.128, streaming) ----
    float4 a0 = z, a1 = z, a2 = z;
    if (rA < B) {
        a0 = __ldcs(xA4 + lane);
        a1 = __ldcs(xA4 + 32 + lane);
        if (lane < Q4 - 64) a2 = __ldcs(xA4 + 64 + lane);
    }

    // ---- sums A -> slot 0 (x in {0,1}: sum == count; FADD on idle pipe) ----
    {
        unsigned char* cb = (unsigned char*)cntw[w][0];
        cb[lane]      = (unsigned char)(int)((a0.x + a0.y) + (a0.z + a0.w));
        cb[32 + lane] = (unsigned char)(int)((a1.x + a1.y) + (a1.z + a1.w));
        if (lane < Q4 - 64)
            cb[64 + lane] = (unsigned char)(int)((a2.x + a2.y) + (a2.z + a2.w));
        else if (lane < 16)
            cb[64 + lane] = 0;               // pad bytes 75..79
        __syncwarp();
    }

    // ---- issue load B early (overlaps bound A) ----
    float4 b0 = z, b1 = z, b2 = z;
    if (rB < B) {
        b0 = __ldcs(xB4 + lane);
        b1 = __ldcs(xB4 + 32 + lane);
        if (lane < Q4 - 64) b2 = __ldcs(xB4 + 64 + lane);
    }

    // ---- bound A ----
    bool flagA;
    {
        float bsum = 0.0f;
        if (lane < NCH16) {
#pragma unroll
            for (int d = 0; d < NDELTA; ++d) {
                const int c = lane - d;
                if (c >= 0) {
                    const unsigned s = __dp4a(cntw[w][0][c], 0x01010101u, 0u);
                    bsum = fmaf(s_M[d], (float)s, bsum);
                }
            }
        }
        flagA = __any_sync(0xFFFFFFFFu,
                           (lane < NCH16) && (bsum >= THETA - MARGIN1));
    }

    // ---- sums B -> slot 1 (B values die before any divergence) ----
    {
        unsigned char* cb = (unsigned char*)cntw[w][1];
        cb[lane]      = (unsigned char)(int)((b0.x + b0.y) + (b0.z + b0.w));
        cb[32 + lane] = (unsigned char)(int)((b1.x + b1.y) + (b1.z + b1.w));
        if (lane < Q4 - 64)
            cb[64 + lane] = (unsigned char)(int)((b2.x + b2.y) + (b2.z + b2.w));
        else if (lane < 16)
            cb[64 + lane] = 0;
        __syncwarp();
    }

    // ---- per-row handler (zero / S2 / S3), identical math to R9b/R10 ----
    auto handle_row = [&](int r, bool flagged) {
        if (r >= B) return;
        float4* or4 = (float4*)(out + (size_t)r * T_LEN);
        if (!flagged) {
            __stcs(or4 + lane, z);
            __stcs(or4 + 32 + lane, z);
            if (lane < Q4 - 64) __stcs(or4 + 64 + lane, z);
            return;
        }
        // rare path: recurrence constants (identical derivation to R1/R5)
        const double f1d = (double)srm[1];
        const double f2d = (double)srm[2];
        const double ddd = f2d / (2.0 * f1d);
        const double Add = f1d / ddd;
        const float dcy = (float)ddd;
        const float Af  = (float)Add;
        const float* xr = x + (size_t)r * T_LEN;

        // S2: warp-parallel windowed overestimate
        float mx = -1e30f;
        if (lane < 30) {
            const int tstart = lane * 10;
            int t0 = tstart - (Ksrm - 1); if (t0 < 0) t0 = 0;
            float s1 = 0.0f, s2 = 0.0f;
            for (int t = t0; t < tstart; ++t) {
                s2 = dcy * (s2 + s1);
                s1 = fmaf(dcy, s1, xr[t]);
            }
#pragma unroll
            for (int t = tstart; t < tstart + 10; ++t) {
                s2 = dcy * (s2 + s1);
                s1 = fmaf(dcy, s1, xr[t]);
                mx = fmaxf(mx, s2);
            }
        }
#pragma unroll
        for (int o = 16; o; o >>= 1)
            mx = fmaxf(mx, __shfl_xor_sync(0xFFFFFFFFu, mx, o));

        if (Af * mx < THETA - MARGIN2) {
            __stcs(or4 + lane, z);
            __stcs(or4 + 32 + lane, z);
            if (lane < Q4 - 64) __stcs(or4 + 64 + lane, z);
        } else if (lane == 0) {
            // S3: full exact scan
            const float dK  = exp2f((float)Ksrm * log2f(dcy));
            const float C2c = Af * dK;
            const float C1c = Af * (float)Ksrm * dK;
            float* orow = out + (size_t)r * T_LEN;

            float s1 = 0.0f, s2 = 0.0f, s1d = 0.0f, s2d = 0.0f;
            float p[PENDN];
#pragma unroll
            for (int j = 0; j < PENDN; ++j) p[j] = 0.0f;

            for (int t = 0; t < T_LEN; ++t) {
                const float xv = xr[t];
                const int j2 = t - Ksrm;
                const float xd = (j2 >= 0) ? xr[j2] : 0.0f;

                s2  = dcy * (s2 + s1);
                s1  = fmaf(dcy, s1, xv);
                s2d = dcy * (s2d + s1d);
                s1d = fmaf(dcy, s1d, xd);

                const float u    = fmaf(-C1c, s1d, fmaf(-C2c, s2d, Af * s2));
                const float ueff = u + p[0];
                const float s    = (ueff >= THETA) ? 1.0f : 0.0f;

#pragma unroll
                for (int j = 0; j < PENDN - 1; ++j)
                    p[j] = fmaf(s, s_rt[j], p[j + 1]);
                p[PENDN - 1] = s * s_rt[PENDN - 1];

                orow[t] = s;
            }
        }
    };

    handle_row(rA, flagA);

    // ---- bound B ----
    bool flagB;
    {
        float bsum = 0.0f;
        if (lane < NCH16) {
#pragma unroll
            for (int d = 0; d < NDELTA; ++d) {
                const int c = lane - d;
                if (c >= 0) {
                    const unsigned s = __dp4a(cntw[w][1][c], 0x01010101u, 0u);
                    bsum = fmaf(s_M[d], (float)s, bsum);
                }
            }
        }
        flagB = __any_sync(0xFFFFFFFFu,
                           (lane < NCH16) && (bsum >= THETA - MARGIN1));
    }

    handle_row(rB, flagB);
}

extern "C" void kernel_launch(void* const* d_in, const int* in_sizes, int n_in,
                              void* d_out, int out_size)
{
    const float* x    = (const float*)d_in[0];
    const float* srm  = (const float*)d_in[1];
    const float* refk = (const float*)d_in[2];
    float* out        = (float*)d_out;

    const int total = in_sizes[0];
    const int B     = total / T_LEN;
    const int Ksrm  = in_sizes[1];
    const int Kref  = in_sizes[2];

    const int grid = (B + RPB - 1) / RPB;
    snn_r11_kernel<<<grid, NTH>>>(x, srm, refk, out, B, Ksrm, Kref);
}

// round 13
// speedup vs baseline: 1.5349x; 1.0666x over previous
#include <cuda_runtime.h>
#include <math.h>

// Fused SNN spike layer (R12 = R11 + 6-wide load batch + 256-thread blocks).
//  Per warp: rows rA, rB. ALL 6 LDG.128 issued back-to-back (MLP=6), then
//  sumsA -> sumsB -> boundA -> handleA -> boundB -> handleB.
//  Counts are float sums (x in {0,1}); bound u <= sum_d M[d]*sum16[C-d] is
//  the direct Hoelder bound (M[d] = max srm tap over chunk-lag range).
//  Refractory <= 0 => unflagged rows never spike -> STG.128 zeros (.cs).
//  S2: flagged -> warp-parallel windowed live-recurrence overestimate;
//      Af*max < theta - 2e-3 => exact u < theta => row exactly zero.
//  S3: else lane 0 full exact scan (R1/R5 arithmetic; rel_err = 0 x7).

#define T_LEN    300
#define Q4       75
#define NTH      256
#define WPB      8
#define RPB      (WPB * 2)     // 16 rows per block
#define NCH16    19
#define PENDN    16
#define NDELTA   8
#define THETA    10.0f
#define MARGIN1  0.02f
#define MARGIN2  2e-3f

__global__ __launch_bounds__(NTH, 6)
void snn_r12_kernel(const float* __restrict__ x,
                    const float* __restrict__ srm,
                    const float* __restrict__ refk,
                    float* __restrict__ out,
                    int B, int Ksrm, int Kref)
{
    __shared__ float s_M[NDELTA];
    __shared__ float s_rt[PENDN];
    __shared__ unsigned int cntw[WPB][2][20];   // double-buffered sums/warp

    const int tid  = threadIdx.x;
    const int lane = tid & 31;
    const int w    = tid >> 5;

    if (tid < PENDN) {
        float v = 0.0f;
        if (tid + 1 < Kref) v = refk[tid + 1];
        s_rt[tid] = v;
    }
    if (tid < NDELTA) {
        int lo = 16 * tid - 15; if (lo < 0) lo = 0;
        int hi = 16 * tid + 15; if (hi > Ksrm - 1) hi = Ksrm - 1;
        float m = 0.0f;
        for (int k = lo; k <= hi; ++k) m = fmaxf(m, srm[k]);
        s_M[tid] = m;
    }
    __syncthreads();   // only block-wide sync

    const float4 z = make_float4(0.f, 0.f, 0.f, 0.f);
    const int rA = blockIdx.x * RPB + w * 2;
    const int rB = rA + 1;

    const float4* xA4 = (const float4*)(x + (size_t)rA * T_LEN);
    const float4* xB4 = (const float4*)(x + (size_t)rB * T_LEN);

    // ---- all 6 loads back-to-back (MLP = 6, streaming) ----
    float4 a0 = z, a1 = z, a2 = z, b0 = z, b1 = z, b2 = z;
    if (rA < B) {
        a0 = __ldcs(xA4 + lane);
        a1 = __ldcs(xA4 + 32 + lane);
        if (lane < Q4 - 64) a2 = __ldcs(xA4 + 64 + lane);
    }
    if (rB < B) {
        b0 = __ldcs(xB4 + lane);
        b1 = __ldcs(xB4 + 32 + lane);
        if (lane < Q4 - 64) b2 = __ldcs(xB4 + 64 + lane);
    }

    // ---- sums A/B -> slots 0/1 (x in {0,1}: sum == count) ----
    {
        unsigned char* ca = (unsigned char*)cntw[w][0];
        ca[lane]      = (unsigned char)(int)((a0.x + a0.y) + (a0.z + a0.w));
        ca[32 + lane] = (unsigned char)(int)((a1.x + a1.y) + (a1.z + a1.w));
        if (lane < Q4 - 64)
            ca[64 + lane] = (unsigned char)(int)((a2.x + a2.y) + (a2.z + a2.w));
        else if (lane < 16)
            ca[64 + lane] = 0;               // pad bytes 75..79
        unsigned char* cb = (unsigned char*)cntw[w][1];
        cb[lane]      = (unsigned char)(int)((b0.x + b0.y) + (b0.z + b0.w));
        cb[32 + lane] = (unsigned char)(int)((b1.x + b1.y) + (b1.z + b1.w));
        if (lane < Q4 - 64)
            cb[64 + lane] = (unsigned char)(int)((b2.x + b2.y) + (b2.z + b2.w));
        else if (lane < 16)
            cb[64 + lane] = 0;
        __syncwarp();
    }

    // ---- bounds A and B ----
    bool flagA, flagB;
    {
        float bsA = 0.0f, bsB = 0.0f;
        if (lane < NCH16) {
#pragma unroll
            for (int d = 0; d < NDELTA; ++d) {
                const int c = lane - d;
                if (c >= 0) {
                    const unsigned sa = __dp4a(cntw[w][0][c], 0x01010101u, 0u);
                    const unsigned sb = __dp4a(cntw[w][1][c], 0x01010101u, 0u);
                    bsA = fmaf(s_M[d], (float)sa, bsA);
                    bsB = fmaf(s_M[d], (float)sb, bsB);
                }
            }
        }
        const bool act = (lane < NCH16);
        flagA = __any_sync(0xFFFFFFFFu, act && (bsA >= THETA - MARGIN1));
        flagB = __any_sync(0xFFFFFFFFu, act && (bsB >= THETA - MARGIN1));
    }

    // ---- per-row handler (zero / S2 / S3), identical math to R9b/R11 ----
    auto handle_row = [&](int r, bool flagged) {
        if (r >= B) return;
        float4* or4 = (float4*)(out + (size_t)r * T_LEN);
        if (!flagged) {
            __stcs(or4 + lane, z);
            __stcs(or4 + 32 + lane, z);
            if (lane < Q4 - 64) __stcs(or4 + 64 + lane, z);
            return;
        }
        // rare path: recurrence constants (identical derivation to R1/R5)
        const double f1d = (double)srm[1];
        const double f2d = (double)srm[2];
        const double ddd = f2d / (2.0 * f1d);
        const double Add = f1d / ddd;
        const float dcy = (float)ddd;
        const float Af  = (float)Add;
        const float* xr = x + (size_t)r * T_LEN;

        // S2: warp-parallel windowed overestimate
        float mx = -1e30f;
        if (lane < 30) {
            const int tstart = lane * 10;
            int t0 = tstart - (Ksrm - 1); if (t0 < 0) t0 = 0;
            float s1 = 0.0f, s2 = 0.0f;
            for (int t = t0; t < tstart; ++t) {
                s2 = dcy * (s2 + s1);
                s1 = fmaf(dcy, s1, xr[t]);
            }
#pragma unroll
            for (int t = tstart; t < tstart + 10; ++t) {
                s2 = dcy * (s2 + s1);
                s1 = fmaf(dcy, s1, xr[t]);
                mx = fmaxf(mx, s2);
            }
        }
#pragma unroll
        for (int o = 16; o; o >>= 1)
            mx = fmaxf(mx, __shfl_xor_sync(0xFFFFFFFFu, mx, o));

        if (Af * mx < THETA - MARGIN2) {
            __stcs(or4 + lane, z);
            __stcs(or4 + 32 + lane, z);
            if (lane < Q4 - 64) __stcs(or4 + 64 + lane, z);
        } else if (lane == 0) {
            // S3: full exact scan
            const float dK  = exp2f((float)Ksrm * log2f(dcy));
            const float C2c = Af * dK;
            const float C1c = Af * (float)Ksrm * dK;
            float* orow = out + (size_t)r * T_LEN;

            float s1 = 0.0f, s2 = 0.0f, s1d = 0.0f, s2d = 0.0f;
            float p[PENDN];
#pragma unroll
            for (int j = 0; j < PENDN; ++j) p[j] = 0.0f;

            for (int t = 0; t < T_LEN; ++t) {
                const float xv = xr[t];
                const int j2 = t - Ksrm;
                const float xd = (j2 >= 0) ? xr[j2] : 0.0f;

                s2  = dcy * (s2 + s1);
                s1  = fmaf(dcy, s1, xv);
                s2d = dcy * (s2d + s1d);
                s1d = fmaf(dcy, s1d, xd);

                const float u    = fmaf(-C1c, s1d, fmaf(-C2c, s2d, Af * s2));
                const float ueff = u + p[0];
                const float s    = (ueff >= THETA) ? 1.0f : 0.0f;

#pragma unroll
                for (int j = 0; j < PENDN - 1; ++j)
                    p[j] = fmaf(s, s_rt[j], p[j + 1]);
                p[PENDN - 1] = s * s_rt[PENDN - 1];

                orow[t] = s;
            }
        }
    };

    handle_row(rA, flagA);
    handle_row(rB, flagB);
}

extern "C" void kernel_launch(void* const* d_in, const int* in_sizes, int n_in,
                              void* d_out, int out_size)
{
    const float* x    = (const float*)d_in[0];
    const float* srm  = (const float*)d_in[1];
    const float* refk = (const float*)d_in[2];
    float* out        = (float*)d_out;

    const int total = in_sizes[0];
    const int B     = total / T_LEN;
    const int Ksrm  = in_sizes[1];
    const int Kref  = in_sizes[2];

    const int grid = (B + RPB - 1) / RPB;
    snn_r12_kernel<<<grid, NTH>>>(x, srm, refk, out, B, Ksrm, Kref);
}